// round 1
// baseline (speedup 1.0000x reference)
#include <cuda_runtime.h>

// PosController_Vectorized: elementwise PID + yaw rotation + clamping over N drones.
// Pure streaming kernel: 17 floats in, 3 floats out per drone. HBM-bound.

#ifndef PC_N
#define PC_N 4194304
#endif

__global__ __launch_bounds__(256)
void pos_controller_kernel(const float4* __restrict__ ref_ve,     // (N,3) as float4 groups of 12B*4
                           const float4* __restrict__ meas_ve,
                           const float4* __restrict__ meas_yaw,   // (N)
                           const float4* __restrict__ mass,       // (N)
                           const float4* __restrict__ pid_int,
                           const float4* __restrict__ pid_prev_err,
                           const float4* __restrict__ pid_prev_d,
                           float4* __restrict__ rp_out,           // (N,2) -> 2 float4 per thread
                           float4* __restrict__ thr_out)          // (N)   -> 1 float4 per thread
{
    const int t = blockIdx.x * blockDim.x + threadIdx.x;   // each thread: 4 drones
    const int nt = PC_N / 4;
    if (t >= nt) return;

    // Constants
    const float G = 9.81f;
    const float DT = 1.0f / 100.0f;
    const float INV_DT = 100.0f;
    const float TAU = 0.05f;
    const float ALPHA = DT / (TAU + DT);
    const float MAX_THRUST = 0.9f * 44.4f;
    const float MAX_ANGLE = 30.0f * 3.14159265358979323846f / 180.0f;
    const float INV_G = 1.0f / G;

    const float KP[3] = {2.0f, 2.0f, 4.0f};
    const float KI[3] = {0.5f, 0.5f, 1.0f};
    const float KD[3] = {0.1f, 0.1f, 0.05f};
    const float LIM = 6.0f;

    // Load 12 floats (4 drones x 3 axes) from each (N,3) tensor as 3 float4s.
    float4 rv[3], mv[3], pi[3], pe[3], pdv[3];
    #pragma unroll
    for (int j = 0; j < 3; ++j) {
        rv[j]  = ref_ve[3 * t + j];
        mv[j]  = meas_ve[3 * t + j];
        pi[j]  = pid_int[3 * t + j];
        pe[j]  = pid_prev_err[3 * t + j];
        pdv[j] = pid_prev_d[3 * t + j];
    }
    const float4 yw = meas_yaw[t];
    const float4 ms = mass[t];

    // Unpack to flat arrays [drone*3 + axis]
    float e[12], I[12], Pd[12], Pe[12];
    {
        const float* rvf = reinterpret_cast<const float*>(rv);
        const float* mvf = reinterpret_cast<const float*>(mv);
        const float* pif = reinterpret_cast<const float*>(pi);
        const float* pef = reinterpret_cast<const float*>(pe);
        const float* pdf = reinterpret_cast<const float*>(pdv);
        #pragma unroll
        for (int k = 0; k < 12; ++k) {
            e[k]  = rvf[k] - mvf[k];
            I[k]  = pif[k];
            Pe[k] = pef[k];
            Pd[k] = pdf[k];
        }
    }

    const float ywf[4] = {yw.x, yw.y, yw.z, yw.w};
    const float msf[4] = {ms.x, ms.y, ms.z, ms.w};

    float rp[8];    // 4 drones x (rp0, rp1)
    float thr[4];

    #pragma unroll
    for (int i = 0; i < 4; ++i) {
        float u[3];
        #pragma unroll
        for (int ax = 0; ax < 3; ++ax) {
            const int k = i * 3 + ax;
            const float err   = e[k];
            const float integ = I[k] + err * DT;
            const float d_raw = (err - Pe[k]) * INV_DT;
            const float d     = Pd[k] + ALPHA * (d_raw - Pd[k]);
            float uu = KP[ax] * err + KI[ax] * integ + KD[ax] * d;
            uu = fminf(fmaxf(uu, -LIM), LIM);
            u[ax] = uu;
        }

        float sy, cy;
        sincosf(ywf[i], &sy, &cy);

        const float rp0 = (sy * u[0] - cy * u[1]) * INV_G;
        const float rp1 = (cy * u[0] + sy * u[1]) * INV_G;

        const float mag = sqrtf(rp0 * rp0 + rp1 * rp1);
        const float s = (mag > MAX_ANGLE) ? fminf(MAX_ANGLE / (mag + 1e-6f), 1.0f) : 1.0f;

        rp[2 * i]     = rp0 * s;
        rp[2 * i + 1] = rp1 * s;

        const float m  = msf[i];
        const float tr = m * G + m * u[2];
        thr[i] = fminf(fmaxf(tr, 0.8f * G * m), MAX_THRUST);
    }

    // Stores: rp (8 floats -> 2 float4), thrust (1 float4)
    rp_out[2 * t]     = make_float4(rp[0], rp[1], rp[2], rp[3]);
    rp_out[2 * t + 1] = make_float4(rp[4], rp[5], rp[6], rp[7]);
    thr_out[t]        = make_float4(thr[0], thr[1], thr[2], thr[3]);
}

extern "C" void kernel_launch(void* const* d_in, const int* in_sizes, int n_in,
                              void* d_out, int out_size)
{
    const float4* ref_ve       = (const float4*)d_in[0];
    const float4* meas_ve      = (const float4*)d_in[1];
    const float4* meas_yaw     = (const float4*)d_in[2];
    const float4* mass         = (const float4*)d_in[3];
    const float4* pid_int      = (const float4*)d_in[4];
    const float4* pid_prev_err = (const float4*)d_in[5];
    const float4* pid_prev_d   = (const float4*)d_in[6];

    float* out = (float*)d_out;
    // Output layout: rp_ref_clamped (N,2) flat first, then thrust_ref (N).
    float4* rp_out  = (float4*)out;                    // 2*N floats = N/2 float4
    float4* thr_out = (float4*)(out + 2 * (size_t)PC_N);

    const int threads = 256;
    const int nt = PC_N / 4;
    const int blocks = (nt + threads - 1) / threads;
    pos_controller_kernel<<<blocks, threads>>>(ref_ve, meas_ve, meas_yaw, mass,
                                               pid_int, pid_prev_err, pid_prev_d,
                                               rp_out, thr_out);
}